// round 1
// baseline (speedup 1.0000x reference)
#include <cuda_runtime.h>
#include <math.h>

// ---------------------------------------------------------------------------
// Problem constants
// ---------------------------------------------------------------------------
#define R_ALL 49152      // B*M*NVIEW = 32*256*6
#define EMBED 1024
#define INDIM 256
#define HID   256
#define BMR   8192       // B*M
#define NSEQ  6
#define G4    1024       // 4*HID
#define LAYERS 3
#define BATCH 32
#define MROWS 256

// ---------------------------------------------------------------------------
// Scratch (device globals: allocation-free, graph-capturable)
// ---------------------------------------------------------------------------
__device__ float g_big [(size_t)R_ALL * EMBED];   // y (stage1 out) then Gin  (201 MB)
__device__ float g_xseq[(size_t)R_ALL * INDIM];   // stage2 out / per-layer h outputs (50 MB)
__device__ float g_gbuf[(size_t)BMR * G4];        // per-step gates (33.5 MB)
__device__ float g_h   [(size_t)BMR * HID];
__device__ float g_c   [(size_t)BMR * HID];
__device__ float g_v   [R_ALL];

// ---------------------------------------------------------------------------
// Generic fp32 SGEMM:  C[m][n] = sum_k A[m][k] * W[n][k]  (+ epilogue)
// A: [M,K] row-major (lda=K-ish), W: [N,K] row-major (ldw), both K-contiguous.
// Tile 128x128, BK=8, 256 threads, 8x8 per thread, double-buffered smem.
// All M,N multiples of 128 and K multiples of 8 in this problem -> no guards.
//
// EPI 0: C = acc + bias1[n]
// EPI 1: C = D[m*ldd+n] + gelu(acc + bias1[n])        (exact erf GELU)
// EPI 2: C = acc + D[m*ldd+n]                          (recurrent: add Gin)
// EPI 3: C = acc + bias1[n] + bias2[n]                 (input proj: bih+bhh)
// ---------------------------------------------------------------------------
#define BM_ 128
#define BN_ 128
#define BK_ 8
#define TM_ 8
#define TN_ 8

__device__ __forceinline__ float gelu_exact(float x) {
    return 0.5f * x * (1.0f + erff(x * 0.70710678118654752f));
}

template<int EPI>
__global__ void __launch_bounds__(256, 2)
sgemm_nt(const float* __restrict__ A, int lda,
         const float* __restrict__ W, int ldw,
         float* __restrict__ C, int ldc,
         int K,
         const float* __restrict__ bias1,
         const float* __restrict__ bias2,
         const float* __restrict__ D, int ldd)
{
    __shared__ float As[2][BK_][BM_];
    __shared__ float Bs[2][BK_][BN_];

    const int tid = threadIdx.x;
    const int m0  = blockIdx.y * BM_;
    const int n0  = blockIdx.x * BN_;

    // global-load mapping: 256 threads, one float4 each per operand tile
    const int lrow = tid >> 1;          // 0..127
    const int lcol = (tid & 1) * 4;     // 0 or 4
    const float* Aptr = A + (size_t)(m0 + lrow) * lda + lcol;
    const float* Wptr = W + (size_t)(n0 + lrow) * ldw + lcol;

    // compute mapping: 16x16 grid of 8x8 microtiles
    const int tm = (tid >> 4) * TM_;
    const int tn = (tid & 15) * TN_;

    float acc[TM_][TN_];
    #pragma unroll
    for (int i = 0; i < TM_; i++)
        #pragma unroll
        for (int j = 0; j < TN_; j++) acc[i][j] = 0.0f;

    // preload tile 0
    {
        float4 a4 = *(const float4*)Aptr;
        float4 b4 = *(const float4*)Wptr;
        As[0][lcol + 0][lrow] = a4.x; As[0][lcol + 1][lrow] = a4.y;
        As[0][lcol + 2][lrow] = a4.z; As[0][lcol + 3][lrow] = a4.w;
        Bs[0][lcol + 0][lrow] = b4.x; Bs[0][lcol + 1][lrow] = b4.y;
        Bs[0][lcol + 2][lrow] = b4.z; Bs[0][lcol + 3][lrow] = b4.w;
    }
    __syncthreads();

    const int KT = K / BK_;
    for (int kt = 0; kt < KT; ++kt) {
        const int cur = kt & 1;
        float4 na, nb;
        const bool more = (kt + 1 < KT);
        if (more) {
            na = *(const float4*)(Aptr + (size_t)(kt + 1) * BK_);
            nb = *(const float4*)(Wptr + (size_t)(kt + 1) * BK_);
        }
        #pragma unroll
        for (int k = 0; k < BK_; ++k) {
            float af[TM_], bf[TN_];
            float4 a0 = *(const float4*)&As[cur][k][tm];
            float4 a1 = *(const float4*)&As[cur][k][tm + 4];
            float4 b0 = *(const float4*)&Bs[cur][k][tn];
            float4 b1 = *(const float4*)&Bs[cur][k][tn + 4];
            af[0]=a0.x; af[1]=a0.y; af[2]=a0.z; af[3]=a0.w;
            af[4]=a1.x; af[5]=a1.y; af[6]=a1.z; af[7]=a1.w;
            bf[0]=b0.x; bf[1]=b0.y; bf[2]=b0.z; bf[3]=b0.w;
            bf[4]=b1.x; bf[5]=b1.y; bf[6]=b1.z; bf[7]=b1.w;
            #pragma unroll
            for (int i = 0; i < TM_; i++)
                #pragma unroll
                for (int j = 0; j < TN_; j++)
                    acc[i][j] = fmaf(af[i], bf[j], acc[i][j]);
        }
        if (more) {
            const int nxt = cur ^ 1;
            As[nxt][lcol + 0][lrow] = na.x; As[nxt][lcol + 1][lrow] = na.y;
            As[nxt][lcol + 2][lrow] = na.z; As[nxt][lcol + 3][lrow] = na.w;
            Bs[nxt][lcol + 0][lrow] = nb.x; Bs[nxt][lcol + 1][lrow] = nb.y;
            Bs[nxt][lcol + 2][lrow] = nb.z; Bs[nxt][lcol + 3][lrow] = nb.w;
        }
        __syncthreads();
    }

    // epilogue
    const int mb = m0 + tm;
    const int nb_ = n0 + tn;
    float bias[TN_];
    if (EPI == 0 || EPI == 1 || EPI == 3) {
        #pragma unroll
        for (int j = 0; j < TN_; j++) {
            bias[j] = bias1[nb_ + j];
            if (EPI == 3) bias[j] += bias2[nb_ + j];
        }
    }
    #pragma unroll
    for (int i = 0; i < TM_; i++) {
        float* crow = C + (size_t)(mb + i) * ldc + nb_;
        const float* drow = (EPI == 1 || EPI == 2)
                          ? (D + (size_t)(mb + i) * ldd + nb_) : nullptr;
        #pragma unroll
        for (int j = 0; j < TN_; j++) {
            float val = acc[i][j];
            if (EPI == 0 || EPI == 3)      val += bias[j];
            else if (EPI == 1)             val = drow[j] + gelu_exact(val + bias[j]);
            else if (EPI == 2)             val += drow[j];
            crow[j] = val;
        }
    }
}

// ---------------------------------------------------------------------------
// LSTM cell: gates G[bm][{i,f,g,o} x 256] -> new h,c ; h also appended to xseq
// ---------------------------------------------------------------------------
__device__ __forceinline__ float sigm(float x) { return 1.0f / (1.0f + expf(-x)); }

__global__ void lstm_cell_kernel(const float* __restrict__ G, int ldg,
                                 float* __restrict__ H, float* __restrict__ Cst,
                                 float* __restrict__ Xout, int t)
{
    int idx = blockIdx.x * blockDim.x + threadIdx.x;
    if (idx >= BMR * HID) return;
    int bm = idx >> 8;
    int h  = idx & 255;
    const float* g = G + (size_t)bm * ldg;
    float gi = g[h];
    float gf = g[256 + h];
    float gg = g[512 + h];
    float go = g[768 + h];
    float cp = Cst[idx];
    float c  = sigm(gf) * cp + sigm(gi) * tanhf(gg);
    float hn = sigm(go) * tanhf(c);
    Cst[idx] = c;
    H[idx]   = hn;
    Xout[((size_t)bm * NSEQ + t) * HID + h] = hn;
}

__global__ void zero_kernel(float* __restrict__ p, int n)
{
    int i = blockIdx.x * blockDim.x + threadIdx.x;
    if (i < n) p[i] = 0.0f;
}

// ---------------------------------------------------------------------------
// v[r] = dot(xseq[r,:256], Wv) + bv   (one warp per row)
// ---------------------------------------------------------------------------
__global__ void viewport_kernel(const float* __restrict__ X,
                                const float* __restrict__ Wv,
                                const float* __restrict__ bv,
                                float* __restrict__ v)
{
    int warp = blockIdx.x * (blockDim.x >> 5) + (threadIdx.x >> 5);
    int lane = threadIdx.x & 31;
    if (warp >= R_ALL) return;
    const float* x = X + (size_t)warp * HID;
    float s = 0.0f;
    #pragma unroll
    for (int k = lane; k < HID; k += 32) s = fmaf(x[k], Wv[k], s);
    #pragma unroll
    for (int o = 16; o > 0; o >>= 1) s += __shfl_down_sync(0xFFFFFFFFu, s, o);
    if (lane == 0) v[warp] = s + bv[0];
}

// ---------------------------------------------------------------------------
// out[b] = bs + (1/M) * sum_m sum_n v[b,m,n] * Ws[n]
// ---------------------------------------------------------------------------
__global__ void score_kernel(const float* __restrict__ v,
                             const float* __restrict__ Ws,
                             const float* __restrict__ bs,
                             float* __restrict__ out)
{
    __shared__ float red[256];
    int b = blockIdx.x;
    int m = threadIdx.x;
    const float* vb = v + ((size_t)b * MROWS + m) * NSEQ;
    float s = 0.0f;
    #pragma unroll
    for (int n = 0; n < NSEQ; n++) s = fmaf(vb[n], Ws[n], s);
    red[m] = s;
    __syncthreads();
    for (int st = 128; st > 0; st >>= 1) {
        if (m < st) red[m] += red[m + st];
        __syncthreads();
    }
    if (m == 0) out[b] = bs[0] + red[0] * (1.0f / (float)MROWS);
}

// ---------------------------------------------------------------------------
// Host orchestration
// ---------------------------------------------------------------------------
static float* sym_addr(const void* symbol)
{
    void* p = nullptr;
    cudaGetSymbolAddress(&p, symbol);
    return (float*)p;
}

extern "C" void kernel_launch(void* const* d_in, const int* in_sizes, int n_in,
                              void* d_out, int out_size)
{
    const float* swin = (const float*)d_in[0];   // [32,256,6,1024]
    const float* conv = (const float*)d_in[1];   // [32,256,6,1024]
    const float* Wc   = (const float*)d_in[2];   // [1024,1024]
    const float* bc   = (const float*)d_in[3];   // [1024]
    const float* Win  = (const float*)d_in[4];   // [256,1024]
    const float* b_in = (const float*)d_in[5];   // [256]
    const float* Wih  = (const float*)d_in[6];   // [3,1024,256]
    const float* Whh  = (const float*)d_in[7];   // [3,1024,256]
    const float* bih  = (const float*)d_in[8];   // [3,1024]
    const float* bhh  = (const float*)d_in[9];   // [3,1024]
    const float* Wv   = (const float*)d_in[10];  // [1,256]
    const float* bv   = (const float*)d_in[11];  // [1]
    const float* Ws   = (const float*)d_in[12];  // [1,6]
    const float* bs   = (const float*)d_in[13];  // [1]
    float* out = (float*)d_out;                  // [32]

    float* big  = sym_addr(g_big);
    float* xseq = sym_addr(g_xseq);
    float* gbuf = sym_addr(g_gbuf);
    float* hbuf = sym_addr(g_h);
    float* cbuf = sym_addr(g_c);
    float* vbuf = sym_addr(g_v);

    const dim3 blk(256);

    // Stage 1: big = swin + gelu(conv @ Wc^T + bc)   [49152,1024]
    {
        dim3 grid(EMBED / BN_, R_ALL / BM_);
        sgemm_nt<1><<<grid, blk>>>(conv, EMBED, Wc, EMBED, big, EMBED, EMBED,
                                   bc, nullptr, swin, EMBED);
    }
    // Stage 2: xseq = big @ Win^T + b_in             [49152,256]
    {
        dim3 grid(INDIM / BN_, R_ALL / BM_);
        sgemm_nt<0><<<grid, blk>>>(big, EMBED, Win, EMBED, xseq, INDIM, EMBED,
                                   b_in, nullptr, nullptr, 0);
    }

    // 3 LSTM layers, seq = 6
    for (int l = 0; l < LAYERS; ++l) {
        const float* Wih_l = Wih + (size_t)l * G4 * INDIM;
        const float* Whh_l = Whh + (size_t)l * G4 * HID;
        const float* bih_l = bih + (size_t)l * G4;
        const float* bhh_l = bhh + (size_t)l * G4;

        // Batched input projection over all 6 timesteps:
        // big(Gin) = xseq @ Wih_l^T + bih + bhh      [49152,1024]
        {
            dim3 grid(G4 / BN_, R_ALL / BM_);
            sgemm_nt<3><<<grid, blk>>>(xseq, INDIM, Wih_l, INDIM, big, G4, INDIM,
                                       bih_l, bhh_l, nullptr, 0);
        }
        // zero h, c
        zero_kernel<<<(BMR * HID + 255) / 256, blk>>>(hbuf, BMR * HID);
        zero_kernel<<<(BMR * HID + 255) / 256, blk>>>(cbuf, BMR * HID);

        for (int t = 0; t < NSEQ; ++t) {
            const float* Gsrc;
            int ldg;
            if (t == 0) {
                // h = 0 -> gates are just Gin rows (bm*6+0), stride 6*1024
                Gsrc = big;           // + t*G4 with t=0
                ldg  = NSEQ * G4;
            } else {
                // gbuf = hbuf @ Whh^T + Gin[:,t,:]
                dim3 grid(G4 / BN_, BMR / BM_);
                sgemm_nt<2><<<grid, blk>>>(hbuf, HID, Whh_l, HID, gbuf, G4, HID,
                                           nullptr, nullptr,
                                           big + (size_t)t * G4, NSEQ * G4);
                Gsrc = gbuf;
                ldg  = G4;
            }
            lstm_cell_kernel<<<(BMR * HID + 255) / 256, blk>>>(
                Gsrc, ldg, hbuf, cbuf, xseq, t);
        }
    }

    // Viewport head: vbuf[r] = xseq[r,:] . Wv + bv
    viewport_kernel<<<R_ALL / 8, blk>>>(xseq, Wv, bv, vbuf);

    // Score head + mean over M -> out[32]
    score_kernel<<<BATCH, blk>>>(vbuf, Ws, bs, out);
    (void)in_sizes; (void)n_in; (void)out_size;
}

// round 3
// speedup vs baseline: 2.4318x; 2.4318x over previous
#include <cuda_runtime.h>
#include <cuda_bf16.h>
#include <math.h>
#include <stdint.h>

// ---------------------------------------------------------------------------
// Problem constants
// ---------------------------------------------------------------------------
#define R_ALL 49152      // B*M*NVIEW
#define EMBED 1024
#define INDIM 256
#define HID   256
#define BMR   8192       // B*M
#define NSEQ  6
#define G4    1024       // 4*HID
#define LAYERS 3
#define BATCH 32
#define MROWS 256

// ---------------------------------------------------------------------------
// Scratch (device globals: allocation-free, graph-capturable)
// ---------------------------------------------------------------------------
__device__ float g_big [(size_t)R_ALL * EMBED];   // stage1 out, then Gin
__device__ float g_xseq[(size_t)R_ALL * INDIM];   // stage2 out / per-layer h
__device__ float g_gbuf[(size_t)BMR * G4];        // per-step gates
__device__ float g_h   [(size_t)BMR * HID];
__device__ float g_c   [(size_t)BMR * HID];
__device__ float g_v   [R_ALL];

// ---------------------------------------------------------------------------
// Helpers
// ---------------------------------------------------------------------------
__device__ __forceinline__ uint32_t smem_u32(const void* p) {
    uint32_t a;
    asm("{ .reg .u64 t; cvta.to.shared.u64 t, %1; cvt.u32.u64 %0, t; }"
        : "=r"(a) : "l"(p));
    return a;
}

// pack two f32 -> bf16x2 (RN); result halves: [lo16 = first arg? see use]
// cvt.rn.bf16x2.f32 d, a, b  ->  d.hi16 = bf16(a), d.lo16 = bf16(b)
#define F2BF2(res, flo, fhi) \
    asm("cvt.rn.bf16x2.f32 %0, %1, %2;" : "=r"(res) : "f"(fhi), "f"(flo))

__device__ __forceinline__ void ldmatrix_x4(uint32_t& r0, uint32_t& r1,
                                            uint32_t& r2, uint32_t& r3,
                                            uint32_t addr) {
    asm volatile("ldmatrix.sync.aligned.m8n8.x4.shared.b16 {%0,%1,%2,%3}, [%4];"
                 : "=r"(r0), "=r"(r1), "=r"(r2), "=r"(r3) : "r"(addr));
}

__device__ __forceinline__ void mma_bf16(float* c, const uint32_t* a,
                                         uint32_t b0, uint32_t b1) {
    asm volatile(
        "mma.sync.aligned.m16n8k16.row.col.f32.bf16.bf16.f32 "
        "{%0,%1,%2,%3}, {%4,%5,%6,%7}, {%8,%9}, {%0,%1,%2,%3};"
        : "+f"(c[0]), "+f"(c[1]), "+f"(c[2]), "+f"(c[3])
        : "r"(a[0]), "r"(a[1]), "r"(a[2]), "r"(a[3]), "r"(b0), "r"(b1));
}

__device__ __forceinline__ float gelu_exact(float x) {
    return 0.5f * x * (1.0f + erff(x * 0.70710678118654752f));
}
__device__ __forceinline__ float sigm(float x) { return 1.0f / (1.0f + expf(-x)); }

// ---------------------------------------------------------------------------
// Split-bf16 tensor-core GEMM via mma.sync (works on baseline compute_100):
//   C[m][n] = sum_k A[m][k] * W[n][k]  (+ epilogue)
// A: [M,K] fp32 row-major, W: [N,K] fp32 row-major.
// Each fp32 x decomposed as hi+lo bf16; 3 MMA products per k-step.
// Tile 128x128, BK=32, 8 warps (4x2), warptile 32x64.
//
// EPI 0: C = acc + bias1[n]
// EPI 1: C = D + gelu(acc + bias1[n])
// EPI 2: C = acc + D
// EPI 3: C = acc + bias1[n] + bias2[n]
// ---------------------------------------------------------------------------
#define TILE_M 128
#define TILE_N 128
#define KC 32
#define SPITCH 40   // halfs per smem row (80 B) -> conflict-free ldmatrix

template<int EPI>
__global__ void __launch_bounds__(256, 2)
bgemm(const float* __restrict__ A, int lda,
      const float* __restrict__ W, int ldw,
      float* __restrict__ C, int ldc, int K,
      const float* __restrict__ bias1,
      const float* __restrict__ bias2,
      const float* __restrict__ D, int ldd)
{
    __shared__ __nv_bfloat16 sAh[TILE_M][SPITCH];
    __shared__ __nv_bfloat16 sAl[TILE_M][SPITCH];
    __shared__ __nv_bfloat16 sBh[TILE_N][SPITCH];
    __shared__ __nv_bfloat16 sBl[TILE_N][SPITCH];

    const int tid  = threadIdx.x;
    const int wid  = tid >> 5;
    const int lane = tid & 31;
    const int wm   = wid & 3;        // warp row: 32 rows each
    const int wn   = wid >> 2;       // warp col: 64 cols each
    const int m0   = blockIdx.y * TILE_M;
    const int n0   = blockIdx.x * TILE_N;

    const uint32_t uAh = smem_u32(sAh);
    const uint32_t uAl = smem_u32(sAl);
    const uint32_t uBh = smem_u32(sBh);
    const uint32_t uBl = smem_u32(sBl);

    float acc[2][8][4];
    #pragma unroll
    for (int i = 0; i < 2; i++)
        #pragma unroll
        for (int j = 0; j < 8; j++)
            #pragma unroll
            for (int q = 0; q < 4; q++) acc[i][j][q] = 0.0f;

    // ldmatrix row/col pattern within a 16x16 region
    const int lrow = lane & 15;            // matrix row supplied by this lane
    const int lkof = (lane >> 4) << 3;     // 0 or 8 (k offset of 8x8 tile)

    const int KT = K / KC;
    for (int kt = 0; kt < KT; ++kt) {
        if (kt) __syncthreads();
        const int k0 = kt * KC;
        // ---- stage A and B: fp32 -> hi/lo bf16 ----
        #pragma unroll
        for (int it = 0; it < 4; ++it) {
            int i   = tid + (it << 8);          // 0..1023
            int row = i >> 3;
            int c4  = (i & 7) << 2;
            float4 v = *(const float4*)(A + (size_t)(m0 + row) * lda + k0 + c4);
            uint32_t h01, h23; F2BF2(h01, v.x, v.y); F2BF2(h23, v.z, v.w);
            float r0 = v.x - __uint_as_float(h01 << 16);
            float r1 = v.y - __uint_as_float(h01 & 0xFFFF0000u);
            float r2 = v.z - __uint_as_float(h23 << 16);
            float r3 = v.w - __uint_as_float(h23 & 0xFFFF0000u);
            uint32_t l01, l23; F2BF2(l01, r0, r1); F2BF2(l23, r2, r3);
            *(uint2*)&sAh[row][c4] = make_uint2(h01, h23);
            *(uint2*)&sAl[row][c4] = make_uint2(l01, l23);
        }
        #pragma unroll
        for (int it = 0; it < 4; ++it) {
            int i   = tid + (it << 8);
            int row = i >> 3;
            int c4  = (i & 7) << 2;
            float4 v = *(const float4*)(W + (size_t)(n0 + row) * ldw + k0 + c4);
            uint32_t h01, h23; F2BF2(h01, v.x, v.y); F2BF2(h23, v.z, v.w);
            float r0 = v.x - __uint_as_float(h01 << 16);
            float r1 = v.y - __uint_as_float(h01 & 0xFFFF0000u);
            float r2 = v.z - __uint_as_float(h23 << 16);
            float r3 = v.w - __uint_as_float(h23 & 0xFFFF0000u);
            uint32_t l01, l23; F2BF2(l01, r0, r1); F2BF2(l23, r2, r3);
            *(uint2*)&sBh[row][c4] = make_uint2(h01, h23);
            *(uint2*)&sBl[row][c4] = make_uint2(l01, l23);
        }
        __syncthreads();

        // ---- compute: 2 k-steps of 16 ----
        #pragma unroll
        for (int ks = 0; ks < 2; ++ks) {
            const uint32_t kbyte = (uint32_t)((ks * 16 + lkof) * 2);
            // A fragments (hi & lo) for both 16-row m-tiles
            uint32_t ah[2][4], al[2][4];
            #pragma unroll
            for (int mt = 0; mt < 2; ++mt) {
                uint32_t roff = (uint32_t)((wm * 32 + mt * 16 + lrow) * (SPITCH * 2)) + kbyte;
                ldmatrix_x4(ah[mt][0], ah[mt][1], ah[mt][2], ah[mt][3], uAh + roff);
                ldmatrix_x4(al[mt][0], al[mt][1], al[mt][2], al[mt][3], uAl + roff);
            }
            // B fragments: 4 pairs of n-tiles (16 n each)
            #pragma unroll
            for (int p = 0; p < 4; ++p) {
                uint32_t roff = (uint32_t)((wn * 64 + p * 16 + lrow) * (SPITCH * 2)) + kbyte;
                uint32_t bh0, bh1, bh2, bh3, bl0, bl1, bl2, bl3;
                ldmatrix_x4(bh0, bh1, bh2, bh3, uBh + roff);
                ldmatrix_x4(bl0, bl1, bl2, bl3, uBl + roff);
                // n-tile 2p   -> regs (r0, r2); n-tile 2p+1 -> (r1, r3)
                #pragma unroll
                for (int mt = 0; mt < 2; ++mt) {
                    mma_bf16(acc[mt][2 * p],     ah[mt], bh0, bh2);  // hi*hi
                    mma_bf16(acc[mt][2 * p],     ah[mt], bl0, bl2);  // hi*lo
                    mma_bf16(acc[mt][2 * p],     al[mt], bh0, bh2);  // lo*hi
                    mma_bf16(acc[mt][2 * p + 1], ah[mt], bh1, bh3);
                    mma_bf16(acc[mt][2 * p + 1], ah[mt], bl1, bl3);
                    mma_bf16(acc[mt][2 * p + 1], al[mt], bh1, bh3);
                }
            }
        }
    }

    // ---- epilogue: registers -> global ----
    const int qrow = lane >> 2;            // 0..7
    const int qcol = (lane & 3) << 1;      // 0,2,4,6
    #pragma unroll
    for (int mt = 0; mt < 2; ++mt) {
        const int gm = m0 + wm * 32 + mt * 16 + qrow;
        #pragma unroll
        for (int nt = 0; nt < 8; ++nt) {
            const int gn = n0 + wn * 64 + nt * 8 + qcol;
            float c0 = acc[mt][nt][0], c1 = acc[mt][nt][1];
            float c2 = acc[mt][nt][2], c3 = acc[mt][nt][3];
            float2 o0, o1;
            if (EPI == 0) {
                float2 b = *(const float2*)(bias1 + gn);
                o0.x = c0 + b.x; o0.y = c1 + b.y;
                o1.x = c2 + b.x; o1.y = c3 + b.y;
            } else if (EPI == 1) {
                float2 b  = *(const float2*)(bias1 + gn);
                float2 d0 = *(const float2*)(D + (size_t)gm * ldd + gn);
                float2 d1 = *(const float2*)(D + (size_t)(gm + 8) * ldd + gn);
                o0.x = d0.x + gelu_exact(c0 + b.x);
                o0.y = d0.y + gelu_exact(c1 + b.y);
                o1.x = d1.x + gelu_exact(c2 + b.x);
                o1.y = d1.y + gelu_exact(c3 + b.y);
            } else if (EPI == 2) {
                float2 d0 = *(const float2*)(D + (size_t)gm * ldd + gn);
                float2 d1 = *(const float2*)(D + (size_t)(gm + 8) * ldd + gn);
                o0.x = c0 + d0.x; o0.y = c1 + d0.y;
                o1.x = c2 + d1.x; o1.y = c3 + d1.y;
            } else { // EPI 3
                float2 b1 = *(const float2*)(bias1 + gn);
                float2 b2 = *(const float2*)(bias2 + gn);
                o0.x = c0 + b1.x + b2.x; o0.y = c1 + b1.y + b2.y;
                o1.x = c2 + b1.x + b2.x; o1.y = c3 + b1.y + b2.y;
            }
            *(float2*)(C + (size_t)gm * ldc + gn)       = o0;
            *(float2*)(C + (size_t)(gm + 8) * ldc + gn) = o1;
        }
    }
}

// ---------------------------------------------------------------------------
// LSTM cell (t==0: zero initial state, no zero kernels needed)
// ---------------------------------------------------------------------------
__global__ void lstm_cell_kernel(const float* __restrict__ G, int ldg,
                                 float* __restrict__ H, float* __restrict__ Cst,
                                 float* __restrict__ Xout, int t)
{
    int idx = blockIdx.x * blockDim.x + threadIdx.x;
    if (idx >= BMR * HID) return;
    int bm = idx >> 8;
    int h  = idx & 255;
    const float* g = G + (size_t)bm * ldg;
    float gi = g[h];
    float gf = g[256 + h];
    float gg = g[512 + h];
    float go = g[768 + h];
    float cp = (t == 0) ? 0.0f : Cst[idx];
    float c  = sigm(gf) * cp + sigm(gi) * tanhf(gg);
    float hn = sigm(go) * tanhf(c);
    Cst[idx] = c;
    H[idx]   = hn;
    Xout[((size_t)bm * NSEQ + t) * HID + h] = hn;
}

// ---------------------------------------------------------------------------
// v[r] = dot(xseq[r,:256], Wv) + bv   (one warp per row)
// ---------------------------------------------------------------------------
__global__ void viewport_kernel(const float* __restrict__ X,
                                const float* __restrict__ Wv,
                                const float* __restrict__ bv,
                                float* __restrict__ v)
{
    int warp = blockIdx.x * (blockDim.x >> 5) + (threadIdx.x >> 5);
    int lane = threadIdx.x & 31;
    if (warp >= R_ALL) return;
    const float* x = X + (size_t)warp * HID;
    float s = 0.0f;
    #pragma unroll
    for (int k = lane; k < HID; k += 32) s = fmaf(x[k], Wv[k], s);
    #pragma unroll
    for (int o = 16; o > 0; o >>= 1) s += __shfl_down_sync(0xFFFFFFFFu, s, o);
    if (lane == 0) v[warp] = s + bv[0];
}

// ---------------------------------------------------------------------------
// out[b] = bs + (1/M) * sum_m sum_n v[b,m,n] * Ws[n]
// ---------------------------------------------------------------------------
__global__ void score_kernel(const float* __restrict__ v,
                             const float* __restrict__ Ws,
                             const float* __restrict__ bs,
                             float* __restrict__ out)
{
    __shared__ float red[256];
    int b = blockIdx.x;
    int m = threadIdx.x;
    const float* vb = v + ((size_t)b * MROWS + m) * NSEQ;
    float s = 0.0f;
    #pragma unroll
    for (int n = 0; n < NSEQ; n++) s = fmaf(vb[n], Ws[n], s);
    red[m] = s;
    __syncthreads();
    for (int st = 128; st > 0; st >>= 1) {
        if (m < st) red[m] += red[m + st];
        __syncthreads();
    }
    if (m == 0) out[b] = bs[0] + red[0] * (1.0f / (float)MROWS);
}

// ---------------------------------------------------------------------------
// Host orchestration
// ---------------------------------------------------------------------------
static float* sym_addr(const void* symbol)
{
    void* p = nullptr;
    cudaGetSymbolAddress(&p, symbol);
    return (float*)p;
}

extern "C" void kernel_launch(void* const* d_in, const int* in_sizes, int n_in,
                              void* d_out, int out_size)
{
    const float* swin = (const float*)d_in[0];   // [32,256,6,1024]
    const float* conv = (const float*)d_in[1];   // [32,256,6,1024]
    const float* Wc   = (const float*)d_in[2];   // [1024,1024]
    const float* bc   = (const float*)d_in[3];   // [1024]
    const float* Win  = (const float*)d_in[4];   // [256,1024]
    const float* b_in = (const float*)d_in[5];   // [256]
    const float* Wih  = (const float*)d_in[6];   // [3,1024,256]
    const float* Whh  = (const float*)d_in[7];   // [3,1024,256]
    const float* bih  = (const float*)d_in[8];   // [3,1024]
    const float* bhh  = (const float*)d_in[9];   // [3,1024]
    const float* Wv   = (const float*)d_in[10];  // [1,256]
    const float* bv   = (const float*)d_in[11];  // [1]
    const float* Ws   = (const float*)d_in[12];  // [1,6]
    const float* bs   = (const float*)d_in[13];  // [1]
    float* out = (float*)d_out;                  // [32]

    float* big  = sym_addr(g_big);
    float* xseq = sym_addr(g_xseq);
    float* gbuf = sym_addr(g_gbuf);
    float* hbuf = sym_addr(g_h);
    float* cbuf = sym_addr(g_c);
    float* vbuf = sym_addr(g_v);

    const dim3 blk(256);

    // Stage 1: big = swin + gelu(conv @ Wc^T + bc)   [49152,1024], K=1024
    {
        dim3 grid(EMBED / TILE_N, R_ALL / TILE_M);
        bgemm<1><<<grid, blk>>>(conv, EMBED, Wc, EMBED, big, EMBED, EMBED,
                                bc, nullptr, swin, EMBED);
    }
    // Stage 2: xseq = big @ Win^T + b_in             [49152,256], K=1024
    {
        dim3 grid(INDIM / TILE_N, R_ALL / TILE_M);
        bgemm<0><<<grid, blk>>>(big, EMBED, Win, EMBED, xseq, INDIM, EMBED,
                                b_in, nullptr, nullptr, 0);
    }

    // 3 LSTM layers, seq = 6
    for (int l = 0; l < LAYERS; ++l) {
        const float* Wih_l = Wih + (size_t)l * G4 * INDIM;
        const float* Whh_l = Whh + (size_t)l * G4 * HID;
        const float* bih_l = bih + (size_t)l * G4;
        const float* bhh_l = bhh + (size_t)l * G4;

        // Batched input projection: big(Gin) = xseq @ Wih^T + bih + bhh [49152,1024]
        {
            dim3 grid(G4 / TILE_N, R_ALL / TILE_M);
            bgemm<3><<<grid, blk>>>(xseq, INDIM, Wih_l, INDIM, big, G4, INDIM,
                                    bih_l, bhh_l, nullptr, 0);
        }

        for (int t = 0; t < NSEQ; ++t) {
            const float* Gsrc;
            int ldg;
            if (t == 0) {
                Gsrc = big;               // h0 = 0: gates = Gin rows, stride 6*1024
                ldg  = NSEQ * G4;
            } else {
                // gbuf = hbuf @ Whh^T + Gin[:,t,:]   [8192,1024], K=256
                dim3 grid(G4 / TILE_N, BMR / TILE_M);
                bgemm<2><<<grid, blk>>>(hbuf, HID, Whh_l, HID, gbuf, G4, HID,
                                        nullptr, nullptr,
                                        big + (size_t)t * G4, NSEQ * G4);
                Gsrc = gbuf;
                ldg  = G4;
            }
            lstm_cell_kernel<<<(BMR * HID + 255) / 256, blk>>>(
                Gsrc, ldg, hbuf, cbuf, xseq, t);
        }
    }

    // Viewport head
    viewport_kernel<<<R_ALL / 8, blk>>>(xseq, Wv, bv, vbuf);
    // Score head + mean over M
    score_kernel<<<BATCH, blk>>>(vbuf, Ws, bs, out);
    (void)in_sizes; (void)n_in; (void)out_size;
}

// round 5
// speedup vs baseline: 2.5332x; 1.0417x over previous
#include <cuda_runtime.h>
#include <cuda_bf16.h>
#include <math.h>
#include <stdint.h>

// ---------------------------------------------------------------------------
// Problem constants
// ---------------------------------------------------------------------------
#define R_ALL 49152      // B*M*NVIEW
#define EMBED 1024
#define INDIM 256
#define HID   256
#define BMR   8192       // B*M
#define NSEQ  6
#define G4    1024       // 4*HID
#define LAYERS 3
#define BATCH 32
#define MROWS 256

// Weight arena offsets (elements)
#define WC_OFF   0
#define WIN_OFF  1048576
#define WIH_OFF  1310720
#define WHH_OFF  2097152
#define W_TOTAL  2883584

// ---------------------------------------------------------------------------
// Scratch (device globals: allocation-free, graph-capturable)
// ---------------------------------------------------------------------------
__device__ float g_big [(size_t)R_ALL * EMBED];       // Gin (fp32)
__device__ float g_gbuf[(size_t)BMR * G4];            // per-step gates (fp32)
__device__ float g_c   [(size_t)BMR * HID];           // cell state
__device__ float g_v   [R_ALL];

__device__ __nv_bfloat16 g_w_hi[W_TOTAL];             // converted weights
__device__ __nv_bfloat16 g_w_lo[W_TOTAL];
__device__ __nv_bfloat16 g_ach[(size_t)R_ALL * EMBED]; // conv hi
__device__ __nv_bfloat16 g_acl[(size_t)R_ALL * EMBED]; // conv lo
__device__ __nv_bfloat16 g_bigh[(size_t)R_ALL * EMBED]; // stage1 out hi
__device__ __nv_bfloat16 g_bigl[(size_t)R_ALL * EMBED]; // stage1 out lo
__device__ __nv_bfloat16 g_xh[(size_t)R_ALL * INDIM];  // xseq hi
__device__ __nv_bfloat16 g_xl[(size_t)R_ALL * INDIM];  // xseq lo
__device__ __nv_bfloat16 g_hh[(size_t)BMR * HID];      // h hi
__device__ __nv_bfloat16 g_hl[(size_t)BMR * HID];      // h lo

// ---------------------------------------------------------------------------
// Helpers
// ---------------------------------------------------------------------------
__device__ __forceinline__ uint32_t smem_u32(const void* p) {
    uint32_t a;
    asm("{ .reg .u64 t; cvta.to.shared.u64 t, %1; cvt.u32.u64 %0, t; }"
        : "=r"(a) : "l"(p));
    return a;
}

#define CP16(dst, src) \
    asm volatile("cp.async.cg.shared.global [%0], [%1], 16;" :: "r"(dst), "l"(src))
#define CP_COMMIT() asm volatile("cp.async.commit_group;")
#define CP_WAIT1()  asm volatile("cp.async.wait_group 1;")

__device__ __forceinline__ void ldmatrix_x4(uint32_t& r0, uint32_t& r1,
                                            uint32_t& r2, uint32_t& r3,
                                            uint32_t addr) {
    asm volatile("ldmatrix.sync.aligned.m8n8.x4.shared.b16 {%0,%1,%2,%3}, [%4];"
                 : "=r"(r0), "=r"(r1), "=r"(r2), "=r"(r3) : "r"(addr));
}

__device__ __forceinline__ void mma_bf16(float* c, const uint32_t* a,
                                         uint32_t b0, uint32_t b1) {
    asm volatile(
        "mma.sync.aligned.m16n8k16.row.col.f32.bf16.bf16.f32 "
        "{%0,%1,%2,%3}, {%4,%5,%6,%7}, {%8,%9}, {%0,%1,%2,%3};"
        : "+f"(c[0]), "+f"(c[1]), "+f"(c[2]), "+f"(c[3])
        : "r"(a[0]), "r"(a[1]), "r"(a[2]), "r"(a[3]), "r"(b0), "r"(b1));
}

__device__ __forceinline__ float gelu_exact(float x) {
    return 0.5f * x * (1.0f + erff(x * 0.70710678118654752f));
}
__device__ __forceinline__ float sigm(float x) { return 1.0f / (1.0f + expf(-x)); }

__device__ __forceinline__ void store_hl(__nv_bfloat16* Bh, __nv_bfloat16* Bl,
                                         size_t off, float x, float y) {
    __nv_bfloat16 hx = __float2bfloat16(x), hy = __float2bfloat16(y);
    float rx = x - __bfloat162float(hx);
    float ry = y - __bfloat162float(hy);
    __nv_bfloat162 hp; hp.x = hx; hp.y = hy;
    __nv_bfloat162 lp; lp.x = __float2bfloat16(rx); lp.y = __float2bfloat16(ry);
    *(__nv_bfloat162*)(Bh + off) = hp;
    *(__nv_bfloat162*)(Bl + off) = lp;
}

// ---------------------------------------------------------------------------
// fp32 -> (hi, lo) bf16 split, vectorized by 4
// ---------------------------------------------------------------------------
__global__ void convert_hl(const float* __restrict__ src,
                           __nv_bfloat16* __restrict__ dh,
                           __nv_bfloat16* __restrict__ dl, int n4)
{
    int i = blockIdx.x * blockDim.x + threadIdx.x;
    if (i >= n4) return;
    float4 v = ((const float4*)src)[i];
    store_hl(dh, dl, (size_t)i * 4,     v.x, v.y);
    store_hl(dh, dl, (size_t)i * 4 + 2, v.z, v.w);
}

// ---------------------------------------------------------------------------
// Split-bf16 tensor-core GEMM via mma.sync + cp.async 3-stage pipeline.
//   C[m][n] = sum_k A[m][k] * W[n][k]  (+ epilogue)
// A, W pre-split into hi/lo bf16 global buffers (K-contiguous rows).
// SMEM per stage: A tile 128 rows x 128B ([32 hi | 32 lo] bf16), B same.
// Swizzle: 16B chunk c (0..7) at phys chunk (c ^ (row & 7)) -> conflict-free
// ldmatrix and cp.async.
//
// MATH 0: val = acc + bias1[n]
// MATH 1: val = D + gelu(acc + bias1[n])
// MATH 2: val = acc + D
// MATH 3: val = acc + bias1[n] + bias2[n]
// OUT 0: fp32 C;  OUT 1: hi/lo bf16 pair
// ---------------------------------------------------------------------------
#define TILE_M 128
#define TILE_N 128
#define KC 32
#define STAGES 3
#define STG_BYTES 32768           // A 16KB + B 16KB
#define SMEM_DYN (STAGES * STG_BYTES)

template<int MATH, int OUT>
__global__ void __launch_bounds__(256, 2)
bgemm(const __nv_bfloat16* __restrict__ Ah, const __nv_bfloat16* __restrict__ Al,
      int lda,
      const __nv_bfloat16* __restrict__ Wh, const __nv_bfloat16* __restrict__ Wl,
      int ldw, int K,
      float* __restrict__ Cf,
      __nv_bfloat16* __restrict__ Chi, __nv_bfloat16* __restrict__ Clo, int ldc,
      const float* __restrict__ bias1, const float* __restrict__ bias2,
      const float* __restrict__ D, int ldd)
{
    extern __shared__ __align__(128) unsigned char dsm[];
    const uint32_t sbase = smem_u32(dsm);

    const int tid  = threadIdx.x;
    const int wid  = tid >> 5;
    const int lane = tid & 31;
    const int wm   = wid & 3;        // warp row: 32 m each
    const int wn   = wid >> 2;       // warp col: 64 n each
    const int m0   = blockIdx.y * TILE_M;
    const int n0   = blockIdx.x * TILE_N;
    const int KT   = K / KC;

    float acc[2][8][4];
    #pragma unroll
    for (int i = 0; i < 2; i++)
        #pragma unroll
        for (int j = 0; j < 8; j++)
            #pragma unroll
            for (int q = 0; q < 4; q++) acc[i][j][q] = 0.0f;

    auto stage_issue = [&](int kt) {
        if (kt < KT) {
            const uint32_t soff = (uint32_t)(kt % STAGES) * STG_BYTES;
            const int k0 = kt * KC;
            #pragma unroll
            for (int i = 0; i < 4; ++i) {           // A: 1024 chunks
                int id  = tid + (i << 8);
                int row = id >> 3, c = id & 7;
                const __nv_bfloat16* src = (c < 4)
                    ? Ah + (size_t)(m0 + row) * lda + k0 + (c << 3)
                    : Al + (size_t)(m0 + row) * lda + k0 + ((c - 4) << 3);
                uint32_t dst = sbase + soff + (uint32_t)(row * 128)
                             + (uint32_t)((c ^ (row & 7)) << 4);
                CP16(dst, src);
            }
            #pragma unroll
            for (int i = 0; i < 4; ++i) {           // B: 1024 chunks
                int id  = tid + (i << 8);
                int row = id >> 3, c = id & 7;
                const __nv_bfloat16* src = (c < 4)
                    ? Wh + (size_t)(n0 + row) * ldw + k0 + (c << 3)
                    : Wl + (size_t)(n0 + row) * ldw + k0 + ((c - 4) << 3);
                uint32_t dst = sbase + soff + 16384u + (uint32_t)(row * 128)
                             + (uint32_t)((c ^ (row & 7)) << 4);
                CP16(dst, src);
            }
        }
        CP_COMMIT();
    };

    stage_issue(0);
    stage_issue(1);

    const int lrow = lane & 15;
    const int lkof = (lane >> 4) << 3;

    for (int kt = 0; kt < KT; ++kt) {
        CP_WAIT1();
        __syncthreads();
        stage_issue(kt + 2);

        const uint32_t aBase = sbase + (uint32_t)(kt % STAGES) * STG_BYTES;
        const uint32_t bBase = aBase + 16384u;

        #pragma unroll
        for (int ks = 0; ks < 2; ++ks) {
            const int kelem = ks * 16 + lkof;
            const int chunk = kelem >> 3;           // 0..3 (hi); +4 = lo
            uint32_t ah[2][4], al[2][4];
            #pragma unroll
            for (int mt = 0; mt < 2; ++mt) {
                const int r = wm * 32 + mt * 16 + lrow;
                const uint32_t rowa = aBase + (uint32_t)(r * 128);
                ldmatrix_x4(ah[mt][0], ah[mt][1], ah[mt][2], ah[mt][3],
                            rowa + (uint32_t)((chunk ^ (r & 7)) << 4));
                ldmatrix_x4(al[mt][0], al[mt][1], al[mt][2], al[mt][3],
                            rowa + (uint32_t)(((chunk + 4) ^ (r & 7)) << 4));
            }
            #pragma unroll
            for (int p = 0; p < 4; ++p) {
                const int r = wn * 64 + p * 16 + lrow;
                const uint32_t rowb = bBase + (uint32_t)(r * 128);
                uint32_t bh0, bh1, bh2, bh3, bl0, bl1, bl2, bl3;
                ldmatrix_x4(bh0, bh1, bh2, bh3,
                            rowb + (uint32_t)((chunk ^ (r & 7)) << 4));
                ldmatrix_x4(bl0, bl1, bl2, bl3,
                            rowb + (uint32_t)(((chunk + 4) ^ (r & 7)) << 4));
                #pragma unroll
                for (int mt = 0; mt < 2; ++mt) {
                    mma_bf16(acc[mt][2 * p],     ah[mt], bh0, bh2);  // hi*hi
                    mma_bf16(acc[mt][2 * p],     ah[mt], bl0, bl2);  // hi*lo
                    mma_bf16(acc[mt][2 * p],     al[mt], bh0, bh2);  // lo*hi
                    mma_bf16(acc[mt][2 * p + 1], ah[mt], bh1, bh3);
                    mma_bf16(acc[mt][2 * p + 1], ah[mt], bl1, bl3);
                    mma_bf16(acc[mt][2 * p + 1], al[mt], bh1, bh3);
                }
            }
        }
    }

    // ---- epilogue ----
    const int qrow = lane >> 2;            // 0..7
    const int qcol = (lane & 3) << 1;      // 0,2,4,6
    #pragma unroll
    for (int mt = 0; mt < 2; ++mt) {
        const int gm = m0 + wm * 32 + mt * 16 + qrow;
        #pragma unroll
        for (int nt = 0; nt < 8; ++nt) {
            const int gn = n0 + wn * 64 + nt * 8 + qcol;
            float c0 = acc[mt][nt][0], c1 = acc[mt][nt][1];
            float c2 = acc[mt][nt][2], c3 = acc[mt][nt][3];
            float2 o0, o1;
            if (MATH == 0) {
                float2 b = *(const float2*)(bias1 + gn);
                o0.x = c0 + b.x; o0.y = c1 + b.y;
                o1.x = c2 + b.x; o1.y = c3 + b.y;
            } else if (MATH == 1) {
                float2 b  = *(const float2*)(bias1 + gn);
                float2 d0 = *(const float2*)(D + (size_t)gm * ldd + gn);
                float2 d1 = *(const float2*)(D + (size_t)(gm + 8) * ldd + gn);
                o0.x = d0.x + gelu_exact(c0 + b.x);
                o0.y = d0.y + gelu_exact(c1 + b.y);
                o1.x = d1.x + gelu_exact(c2 + b.x);
                o1.y = d1.y + gelu_exact(c3 + b.y);
            } else if (MATH == 2) {
                float2 d0 = *(const float2*)(D + (size_t)gm * ldd + gn);
                float2 d1 = *(const float2*)(D + (size_t)(gm + 8) * ldd + gn);
                o0.x = c0 + d0.x; o0.y = c1 + d0.y;
                o1.x = c2 + d1.x; o1.y = c3 + d1.y;
            } else {
                float2 b1 = *(const float2*)(bias1 + gn);
                float2 b2 = *(const float2*)(bias2 + gn);
                o0.x = c0 + b1.x + b2.x; o0.y = c1 + b1.y + b2.y;
                o1.x = c2 + b1.x + b2.x; o1.y = c3 + b1.y + b2.y;
            }
            if (OUT == 0) {
                *(float2*)(Cf + (size_t)gm * ldc + gn)       = o0;
                *(float2*)(Cf + (size_t)(gm + 8) * ldc + gn) = o1;
            } else {
                store_hl(Chi, Clo, (size_t)gm * ldc + gn,       o0.x, o0.y);
                store_hl(Chi, Clo, (size_t)(gm + 8) * ldc + gn, o1.x, o1.y);
            }
        }
    }
}

// ---------------------------------------------------------------------------
// LSTM cell: gates fp32 -> h (hi/lo), c, xseq slot t (hi/lo)
// ---------------------------------------------------------------------------
__global__ void lstm_cell_kernel(const float* __restrict__ G, int ldg,
                                 __nv_bfloat16* __restrict__ Hh,
                                 __nv_bfloat16* __restrict__ Hl,
                                 float* __restrict__ Cst,
                                 __nv_bfloat16* __restrict__ Xh,
                                 __nv_bfloat16* __restrict__ Xl, int t)
{
    int idx = blockIdx.x * blockDim.x + threadIdx.x;
    if (idx >= BMR * HID) return;
    int bm = idx >> 8;
    int h  = idx & 255;
    const float* g = G + (size_t)bm * ldg;
    float gi = g[h];
    float gf = g[256 + h];
    float gg = g[512 + h];
    float go = g[768 + h];
    float cp = (t == 0) ? 0.0f : Cst[idx];
    float c  = sigm(gf) * cp + sigm(gi) * tanhf(gg);
    float hn = sigm(go) * tanhf(c);
    Cst[idx] = c;
    __nv_bfloat16 hb = __float2bfloat16(hn);
    float rl = hn - __bfloat162float(hb);
    __nv_bfloat16 lb = __float2bfloat16(rl);
    Hh[idx] = hb;
    Hl[idx] = lb;
    size_t xo = ((size_t)bm * NSEQ + t) * HID + h;
    Xh[xo] = hb;
    Xl[xo] = lb;
}

// ---------------------------------------------------------------------------
// v[r] = dot(x[r,:256], Wv) + bv, x = hi + lo   (one warp per row)
// ---------------------------------------------------------------------------
__global__ void viewport_kernel(const __nv_bfloat16* __restrict__ Xh,
                                const __nv_bfloat16* __restrict__ Xl,
                                const float* __restrict__ Wv,
                                const float* __restrict__ bv,
                                float* __restrict__ v)
{
    int warp = blockIdx.x * (blockDim.x >> 5) + (threadIdx.x >> 5);
    int lane = threadIdx.x & 31;
    if (warp >= R_ALL) return;
    const __nv_bfloat16* xh = Xh + (size_t)warp * HID;
    const __nv_bfloat16* xl = Xl + (size_t)warp * HID;
    float s = 0.0f;
    #pragma unroll
    for (int k = lane; k < HID; k += 32) {
        float x = __bfloat162float(xh[k]) + __bfloat162float(xl[k]);
        s = fmaf(x, Wv[k], s);
    }
    #pragma unroll
    for (int o = 16; o > 0; o >>= 1) s += __shfl_down_sync(0xFFFFFFFFu, s, o);
    if (lane == 0) v[warp] = s + bv[0];
}

// ---------------------------------------------------------------------------
// out[b] = bs + (1/M) * sum_m sum_n v[b,m,n] * Ws[n]
// ---------------------------------------------------------------------------
__global__ void score_kernel(const float* __restrict__ v,
                             const float* __restrict__ Ws,
                             const float* __restrict__ bs,
                             float* __restrict__ out)
{
    __shared__ float red[256];
    int b = blockIdx.x;
    int m = threadIdx.x;
    const float* vb = v + ((size_t)b * MROWS + m) * NSEQ;
    float s = 0.0f;
    #pragma unroll
    for (int n = 0; n < NSEQ; n++) s = fmaf(vb[n], Ws[n], s);
    red[m] = s;
    __syncthreads();
    for (int st = 128; st > 0; st >>= 1) {
        if (m < st) red[m] += red[m + st];
        __syncthreads();
    }
    if (m == 0) out[b] = bs[0] + red[0] * (1.0f / (float)MROWS);
}

// ---------------------------------------------------------------------------
// Host orchestration
// ---------------------------------------------------------------------------
template<typename T>
static T* sym_addr(const void* symbol)
{
    void* p = nullptr;
    cudaGetSymbolAddress(&p, symbol);
    return (T*)p;
}

extern "C" void kernel_launch(void* const* d_in, const int* in_sizes, int n_in,
                              void* d_out, int out_size)
{
    const float* swin = (const float*)d_in[0];
    const float* conv = (const float*)d_in[1];
    const float* Wc   = (const float*)d_in[2];
    const float* bc   = (const float*)d_in[3];
    const float* Win  = (const float*)d_in[4];
    const float* b_in = (const float*)d_in[5];
    const float* Wih  = (const float*)d_in[6];
    const float* Whh  = (const float*)d_in[7];
    const float* bih  = (const float*)d_in[8];
    const float* bhh  = (const float*)d_in[9];
    const float* Wv   = (const float*)d_in[10];
    const float* bv   = (const float*)d_in[11];
    const float* Ws   = (const float*)d_in[12];
    const float* bs   = (const float*)d_in[13];
    float* out = (float*)d_out;

    float* big  = sym_addr<float>(g_big);
    float* gbuf = sym_addr<float>(g_gbuf);
    float* cbuf = sym_addr<float>(g_c);
    float* vbuf = sym_addr<float>(g_v);
    __nv_bfloat16* whi  = sym_addr<__nv_bfloat16>(g_w_hi);
    __nv_bfloat16* wlo  = sym_addr<__nv_bfloat16>(g_w_lo);
    __nv_bfloat16* ach  = sym_addr<__nv_bfloat16>(g_ach);
    __nv_bfloat16* acl  = sym_addr<__nv_bfloat16>(g_acl);
    __nv_bfloat16* bigh = sym_addr<__nv_bfloat16>(g_bigh);
    __nv_bfloat16* bigl = sym_addr<__nv_bfloat16>(g_bigl);
    __nv_bfloat16* xh   = sym_addr<__nv_bfloat16>(g_xh);
    __nv_bfloat16* xl   = sym_addr<__nv_bfloat16>(g_xl);
    __nv_bfloat16* hh   = sym_addr<__nv_bfloat16>(g_hh);
    __nv_bfloat16* hl   = sym_addr<__nv_bfloat16>(g_hl);

    cudaFuncSetAttribute(bgemm<1,1>, cudaFuncAttributeMaxDynamicSharedMemorySize, SMEM_DYN);
    cudaFuncSetAttribute(bgemm<0,1>, cudaFuncAttributeMaxDynamicSharedMemorySize, SMEM_DYN);
    cudaFuncSetAttribute(bgemm<3,0>, cudaFuncAttributeMaxDynamicSharedMemorySize, SMEM_DYN);
    cudaFuncSetAttribute(bgemm<2,0>, cudaFuncAttributeMaxDynamicSharedMemorySize, SMEM_DYN);

    const dim3 blk(256);

    // ---- prep: split weights + conv activations into bf16 hi/lo ----
    convert_hl<<<(R_ALL * EMBED / 4 + 255) / 256, blk>>>(conv, ach, acl, R_ALL * EMBED / 4);
    convert_hl<<<(1048576 / 4 + 255) / 256, blk>>>(Wc,  whi + WC_OFF,  wlo + WC_OFF,  1048576 / 4);
    convert_hl<<<(262144  / 4 + 255) / 256, blk>>>(Win, whi + WIN_OFF, wlo + WIN_OFF, 262144 / 4);
    convert_hl<<<(786432  / 4 + 255) / 256, blk>>>(Wih, whi + WIH_OFF, wlo + WIH_OFF, 786432 / 4);
    convert_hl<<<(786432  / 4 + 255) / 256, blk>>>(Whh, whi + WHH_OFF, wlo + WHH_OFF, 786432 / 4);

    // Stage 1: big_hl = swin + gelu(conv @ Wc^T + bc)   [49152,1024], K=1024
    {
        dim3 grid(EMBED / TILE_N, R_ALL / TILE_M);
        bgemm<1,1><<<grid, blk, SMEM_DYN>>>(ach, acl, EMBED,
                                            whi + WC_OFF, wlo + WC_OFF, EMBED, EMBED,
                                            nullptr, bigh, bigl, EMBED,
                                            bc, nullptr, swin, EMBED);
    }
    // Stage 2: xseq_hl = big @ Win^T + b_in             [49152,256], K=1024
    {
        dim3 grid(INDIM / TILE_N, R_ALL / TILE_M);
        bgemm<0,1><<<grid, blk, SMEM_DYN>>>(bigh, bigl, EMBED,
                                            whi + WIN_OFF, wlo + WIN_OFF, EMBED, EMBED,
                                            nullptr, xh, xl, INDIM,
                                            b_in, nullptr, nullptr, 0);
    }

    for (int l = 0; l < LAYERS; ++l) {
        const __nv_bfloat16* Wih_h = whi + WIH_OFF + (size_t)l * G4 * INDIM;
        const __nv_bfloat16* Wih_l = wlo + WIH_OFF + (size_t)l * G4 * INDIM;
        const __nv_bfloat16* Whh_h = whi + WHH_OFF + (size_t)l * G4 * HID;
        const __nv_bfloat16* Whh_l = wlo + WHH_OFF + (size_t)l * G4 * HID;
        const float* bih_l = bih + (size_t)l * G4;
        const float* bhh_l = bhh + (size_t)l * G4;

        // Gin = xseq @ Wih^T + bih + bhh    [49152,1024], K=256
        {
            dim3 grid(G4 / TILE_N, R_ALL / TILE_M);
            bgemm<3,0><<<grid, blk, SMEM_DYN>>>(xh, xl, INDIM,
                                                Wih_h, Wih_l, INDIM, INDIM,
                                                big, nullptr, nullptr, G4,
                                                bih_l, bhh_l, nullptr, 0);
        }

        for (int t = 0; t < NSEQ; ++t) {
            const float* Gsrc;
            int ldg;
            if (t == 0) {
                Gsrc = big;               // h0 = 0: gates = Gin rows, stride 6*1024
                ldg  = NSEQ * G4;
            } else {
                // gbuf = h @ Whh^T + Gin[:,t,:]    [8192,1024], K=256
                dim3 grid(G4 / TILE_N, BMR / TILE_M);
                bgemm<2,0><<<grid, blk, SMEM_DYN>>>(hh, hl, HID,
                                                    Whh_h, Whh_l, HID, HID,
                                                    gbuf, nullptr, nullptr, G4,
                                                    nullptr, nullptr,
                                                    big + (size_t)t * G4, NSEQ * G4);
                Gsrc = gbuf;
                ldg  = G4;
            }
            lstm_cell_kernel<<<(BMR * HID + 255) / 256, blk>>>(
                Gsrc, ldg, hh, hl, cbuf, xh, xl, t);
        }
    }

    viewport_kernel<<<R_ALL / 8, blk>>>(xh, xl, Wv, bv, vbuf);
    score_kernel<<<BATCH, blk>>>(vbuf, Ws, bs, out);
    (void)in_sizes; (void)n_in; (void)out_size;
}

// round 6
// speedup vs baseline: 2.8011x; 1.1057x over previous
#include <cuda_runtime.h>
#include <cuda_fp16.h>
#include <math.h>
#include <stdint.h>

// ---------------------------------------------------------------------------
// Problem constants
// ---------------------------------------------------------------------------
#define R_ALL 49152      // B*M*NVIEW
#define EMBED 1024
#define INDIM 256
#define HID   256
#define BMR   8192       // B*M
#define NSEQ  6
#define G4    1024       // 4*HID
#define LAYERS 3
#define BATCH 32
#define MROWS 256

// Weight arena offsets (elements)
#define WC_OFF   0
#define WIN_OFF  1048576
#define WIH_OFF  1310720
#define WHH_OFF  2097152
#define W_TOTAL  2883584

// ---------------------------------------------------------------------------
// Scratch (device globals: allocation-free, graph-capturable)
// ---------------------------------------------------------------------------
__device__ float g_big [(size_t)R_ALL * EMBED];     // Gin (fp32, gate-interleaved)
__device__ float g_c   [(size_t)BMR * HID];         // cell state
__device__ float g_v   [R_ALL];
__device__ float g_bsum[LAYERS * G4];               // permuted bih+bhh

__device__ __align__(16) __half g_whi[W_TOTAL];     // weight hi (LSTM W gate-interleaved)
__device__ __align__(16) __half g_wlo[W_TOTAL];     // weight lo
__device__ __align__(16) __half g_ach [(size_t)R_ALL * EMBED];  // conv fp16
__device__ __align__(16) __half g_bigh[(size_t)R_ALL * EMBED];  // stage1 out fp16
__device__ __align__(16) __half g_xh  [(size_t)R_ALL * INDIM];  // xseq fp16

// ---------------------------------------------------------------------------
// Helpers
// ---------------------------------------------------------------------------
__device__ __forceinline__ uint32_t smem_u32(const void* p) {
    uint32_t a;
    asm("{ .reg .u64 t; cvta.to.shared.u64 t, %1; cvt.u32.u64 %0, t; }"
        : "=r"(a) : "l"(p));
    return a;
}

#define CP16(dst, src) \
    asm volatile("cp.async.cg.shared.global [%0], [%1], 16;" :: "r"(dst), "l"(src))
#define CP_COMMIT() asm volatile("cp.async.commit_group;")
#define CP_WAIT1()  asm volatile("cp.async.wait_group 1;")

__device__ __forceinline__ void ldmatrix_x4(uint32_t& r0, uint32_t& r1,
                                            uint32_t& r2, uint32_t& r3,
                                            uint32_t addr) {
    asm volatile("ldmatrix.sync.aligned.m8n8.x4.shared.b16 {%0,%1,%2,%3}, [%4];"
                 : "=r"(r0), "=r"(r1), "=r"(r2), "=r"(r3) : "r"(addr));
}

__device__ __forceinline__ void mma_fp16(float* c, const uint32_t* a,
                                         uint32_t b0, uint32_t b1) {
    asm volatile(
        "mma.sync.aligned.m16n8k16.row.col.f32.f16.f16.f32 "
        "{%0,%1,%2,%3}, {%4,%5,%6,%7}, {%8,%9}, {%0,%1,%2,%3};"
        : "+f"(c[0]), "+f"(c[1]), "+f"(c[2]), "+f"(c[3])
        : "r"(a[0]), "r"(a[1]), "r"(a[2]), "r"(a[3]), "r"(b0), "r"(b1));
}

__device__ __forceinline__ float gelu_exact(float x) {
    return 0.5f * x * (1.0f + erff(x * 0.70710678118654752f));
}
__device__ __forceinline__ float sigm(float x) { return 1.0f / (1.0f + expf(-x)); }

// ---------------------------------------------------------------------------
// Prep kernels
// ---------------------------------------------------------------------------
// fp32 activations -> fp16 (single rounding; random error, averages out)
__global__ void convert_act(const float* __restrict__ src,
                            __half* __restrict__ dst, int n4)
{
    int i = blockIdx.x * blockDim.x + threadIdx.x;
    if (i >= n4) return;
    float4 v = ((const float4*)src)[i];
    __half2* d = (__half2*)(dst + (size_t)i * 4);
    d[0] = __floats2half2_rn(v.x, v.y);
    d[1] = __floats2half2_rn(v.z, v.w);
}

// fp32 weights -> fp16 hi + fp16 lo (systematic error eliminated).
// perm=1: gate-interleave rows: r(gate g=r>>8, unit u=r&255) -> u*4+g
__global__ void convert_w(const float* __restrict__ src,
                          __half* __restrict__ dh, __half* __restrict__ dl,
                          int rows, int K, int perm)
{
    int idx = blockIdx.x * blockDim.x + threadIdx.x;
    int n = rows * (K / 4);
    if (idx >= n) return;
    int r  = idx / (K / 4);
    int kk = (idx % (K / 4)) * 4;
    int nr = perm ? ((r & 255) * 4 + (r >> 8)) : r;
    float4 v = *(const float4*)(src + (size_t)r * K + kk);
    __half h0 = __float2half(v.x), h1 = __float2half(v.y);
    __half h2 = __float2half(v.z), h3 = __float2half(v.w);
    __half2* ph = (__half2*)(dh + (size_t)nr * K + kk);
    __half2* pl = (__half2*)(dl + (size_t)nr * K + kk);
    ph[0] = __halves2half2(h0, h1);
    ph[1] = __halves2half2(h2, h3);
    pl[0] = __floats2half2_rn(v.x - __half2float(h0), v.y - __half2float(h1));
    pl[1] = __floats2half2_rn(v.z - __half2float(h2), v.w - __half2float(h3));
}

// bsum[l, u*4+g] = bih[l, g*256+u] + bhh[l, g*256+u]
__global__ void bias_perm(const float* __restrict__ bih,
                          const float* __restrict__ bhh,
                          float* __restrict__ bsum)
{
    int idx = blockIdx.x * blockDim.x + threadIdx.x;
    if (idx >= LAYERS * G4) return;
    int l = idx >> 10;
    int r = idx & 1023;
    int nr = (r & 255) * 4 + (r >> 8);
    bsum[l * G4 + nr] = bih[idx] + bhh[idx];
}

// ---------------------------------------------------------------------------
// GEMM: C[m][n] = sum_k A[m][k]*(Wh[n][k]+Wl[n][k]) (+ epilogue)
// A: fp16 single. W: fp16 hi/lo. 2 MMA products per k16.
// Tile 128x128, K chunk 64, 2-stage cp.async pipeline.
// SMEM/stage: A 128x128B (64 fp16/row), B 2 sub-tiles x 128x128B (32hi|32lo).
// Swizzle: chunk c at phys (c ^ (row&7)).
//
// MATH 0: val = acc + bias1[n]
// MATH 1: val = D + gelu(acc + bias1[n])                    (stage1)
// MATH 4: fused LSTM cell (gate-interleaved cols; D=Gin slice)
// OUT 0: fp32 C;  OUT 1: fp16 C
// ---------------------------------------------------------------------------
#define TILE_M 128
#define TILE_N 128
#define KC2 64
#define STG_BYTES 49152          // A 16KB + B 32KB
#define SMEM_DYN (2 * STG_BYTES)

template<int MATH, int OUT>
__global__ void __launch_bounds__(256, 2)
fgemm(const __half* __restrict__ A, int lda,
      const __half* __restrict__ Wh, const __half* __restrict__ Wl,
      int ldw, int K,
      float* __restrict__ Cf, __half* __restrict__ Ch, int ldc,
      const float* __restrict__ bias1,
      const float* __restrict__ D, int ldd,
      float* __restrict__ cst, __half* __restrict__ Xh, int t)
{
    extern __shared__ __align__(128) unsigned char dsm[];
    const uint32_t sbase = smem_u32(dsm);

    const int tid  = threadIdx.x;
    const int wid  = tid >> 5;
    const int lane = tid & 31;
    const int wm   = wid & 3;        // warp row: 32 m
    const int wn   = wid >> 2;       // warp col: 64 n
    const int m0   = blockIdx.y * TILE_M;
    const int n0   = blockIdx.x * TILE_N;
    const int KT2  = K / KC2;

    float acc[2][8][4];
    #pragma unroll
    for (int i = 0; i < 2; i++)
        #pragma unroll
        for (int j = 0; j < 8; j++)
            #pragma unroll
            for (int q = 0; q < 4; q++) acc[i][j][q] = 0.0f;

    auto stage_issue = [&](int kt2) {
        if (kt2 < KT2) {
            const uint32_t soff = (uint32_t)(kt2 & 1) * STG_BYTES;
            const int k0 = kt2 * KC2;
            #pragma unroll
            for (int i = 0; i < 4; ++i) {            // A: 1024 16B chunks
                int id  = tid + (i << 8);
                int row = id >> 3, c = id & 7;
                const __half* src = A + (size_t)(m0 + row) * lda + k0 + (c << 3);
                uint32_t dst = sbase + soff + (uint32_t)(row * 128)
                             + (uint32_t)((c ^ (row & 7)) << 4);
                CP16(dst, src);
            }
            #pragma unroll
            for (int i = 0; i < 8; ++i) {            // B: 2048 chunks
                int id  = tid + (i << 8);
                int sub = id >> 10;
                int rid = id & 1023;
                int row = rid >> 3, c = rid & 7;
                int kk  = k0 + sub * 32;
                const __half* src = (c < 4)
                    ? Wh + (size_t)(n0 + row) * ldw + kk + (c << 3)
                    : Wl + (size_t)(n0 + row) * ldw + kk + ((c - 4) << 3);
                uint32_t dst = sbase + soff + 16384u + (uint32_t)(sub << 14)
                             + (uint32_t)(row * 128)
                             + (uint32_t)((c ^ (row & 7)) << 4);
                CP16(dst, src);
            }
        }
        CP_COMMIT();
    };

    stage_issue(0);

    const int lrow = lane & 15;
    const int lk3  = (lane >> 4);       // 0 or 1 (k-offset 8 within 16)

    for (int kt2 = 0; kt2 < KT2; ++kt2) {
        stage_issue(kt2 + 1);
        CP_WAIT1();
        __syncthreads();

        const uint32_t aBase = sbase + (uint32_t)(kt2 & 1) * STG_BYTES;

        #pragma unroll
        for (int ks = 0; ks < 4; ++ks) {
            const int chunkA = ks * 2 + lk3;                 // 0..7
            const int sub    = ks >> 1;
            const int chunkB = (ks & 1) * 2 + lk3;           // 0..3 (hi); +4 lo
            const uint32_t bBase = aBase + 16384u + (uint32_t)(sub << 14);

            uint32_t af[2][4];
            #pragma unroll
            for (int mt = 0; mt < 2; ++mt) {
                const int r = wm * 32 + mt * 16 + lrow;
                ldmatrix_x4(af[mt][0], af[mt][1], af[mt][2], af[mt][3],
                            aBase + (uint32_t)(r * 128)
                                  + (uint32_t)((chunkA ^ (r & 7)) << 4));
            }
            #pragma unroll
            for (int p = 0; p < 4; ++p) {
                const int r = wn * 64 + p * 16 + lrow;
                const uint32_t rowb = bBase + (uint32_t)(r * 128);
                uint32_t bh0, bh1, bh2, bh3, bl0, bl1, bl2, bl3;
                ldmatrix_x4(bh0, bh1, bh2, bh3,
                            rowb + (uint32_t)((chunkB ^ (r & 7)) << 4));
                ldmatrix_x4(bl0, bl1, bl2, bl3,
                            rowb + (uint32_t)(((chunkB + 4) ^ (r & 7)) << 4));
                #pragma unroll
                for (int mt = 0; mt < 2; ++mt) {
                    mma_fp16(acc[mt][2 * p],     af[mt], bh0, bh2);
                    mma_fp16(acc[mt][2 * p],     af[mt], bl0, bl2);
                    mma_fp16(acc[mt][2 * p + 1], af[mt], bh1, bh3);
                    mma_fp16(acc[mt][2 * p + 1], af[mt], bl1, bl3);
                }
            }
        }
        __syncthreads();
    }

    // ---- epilogue ----
    const int qrow = lane >> 2;            // 0..7
    const int qcol = (lane & 3) << 1;      // 0,2,4,6
    #pragma unroll
    for (int mt = 0; mt < 2; ++mt) {
        const int gm = m0 + wm * 32 + mt * 16 + qrow;
        #pragma unroll
        for (int nt = 0; nt < 8; ++nt) {
            const int gn = n0 + wn * 64 + nt * 8 + qcol;
            float c0 = acc[mt][nt][0], c1 = acc[mt][nt][1];
            float c2 = acc[mt][nt][2], c3 = acc[mt][nt][3];

            if (MATH == 4) {
                // fused LSTM cell (gate-interleaved columns)
                float2 d0 = *(const float2*)(D + (size_t)gm * ldd + gn);
                float2 d1 = *(const float2*)(D + (size_t)(gm + 8) * ldd + gn);
                float v0 = c0 + d0.x, v1 = c1 + d0.y;
                float v2 = c2 + d1.x, v3 = c3 + d1.y;
                float e0 = __shfl_xor_sync(0xFFFFFFFFu, v0, 1);
                float e1 = __shfl_xor_sync(0xFFFFFFFFu, v1, 1);
                float e2 = __shfl_xor_sync(0xFFFFFFFFu, v2, 1);
                float e3 = __shfl_xor_sync(0xFFFFFFFFu, v3, 1);
                float gi, gf, gg, go; int row;
                if (!(lane & 1)) { gi = v0; gf = v1; gg = e0; go = e1; row = gm; }
                else             { gi = e2; gf = e3; gg = v2; go = v3; row = gm + 8; }
                const int u = gn >> 2;
                const size_t co = (size_t)row * HID + u;
                float cp = cst[co];
                float cn = sigm(gf) * cp + sigm(gi) * tanhf(gg);
                float hn = sigm(go) * tanhf(cn);
                cst[co] = cn;
                Xh[((size_t)row * NSEQ + t) * HID + u] = __float2half(hn);
                continue;
            }

            float2 o0, o1;
            if (MATH == 0) {
                float2 b = *(const float2*)(bias1 + gn);
                o0.x = c0 + b.x; o0.y = c1 + b.y;
                o1.x = c2 + b.x; o1.y = c3 + b.y;
            } else { // MATH 1
                float2 b  = *(const float2*)(bias1 + gn);
                float2 d0 = *(const float2*)(D + (size_t)gm * ldd + gn);
                float2 d1 = *(const float2*)(D + (size_t)(gm + 8) * ldd + gn);
                o0.x = d0.x + gelu_exact(c0 + b.x);
                o0.y = d0.y + gelu_exact(c1 + b.y);
                o1.x = d1.x + gelu_exact(c2 + b.x);
                o1.y = d1.y + gelu_exact(c3 + b.y);
            }
            if (OUT == 0) {
                *(float2*)(Cf + (size_t)gm * ldc + gn)       = o0;
                *(float2*)(Cf + (size_t)(gm + 8) * ldc + gn) = o1;
            } else {
                *(__half2*)(Ch + (size_t)gm * ldc + gn) =
                    __floats2half2_rn(o0.x, o0.y);
                *(__half2*)(Ch + (size_t)(gm + 8) * ldc + gn) =
                    __floats2half2_rn(o1.x, o1.y);
            }
        }
    }
}

// ---------------------------------------------------------------------------
// LSTM t=0 cell on interleaved Gin (h0=c0=0)
// ---------------------------------------------------------------------------
__global__ void lstm_t0(const float* __restrict__ G, int ldg,
                        float* __restrict__ cst, __half* __restrict__ Xh)
{
    int idx = blockIdx.x * blockDim.x + threadIdx.x;
    if (idx >= BMR * HID) return;
    int bm = idx >> 8;
    int u  = idx & 255;
    float4 g = *(const float4*)(G + (size_t)bm * ldg + 4 * u);  // i,f,g,o
    float c = sigm(g.x) * tanhf(g.z);
    float h = sigm(g.w) * tanhf(c);
    cst[idx] = c;
    Xh[(size_t)bm * NSEQ * HID + u] = __float2half(h);   // slot t=0
}

// ---------------------------------------------------------------------------
// Heads
// ---------------------------------------------------------------------------
__global__ void viewport_kernel(const __half* __restrict__ X,
                                const float* __restrict__ Wv,
                                const float* __restrict__ bv,
                                float* __restrict__ v)
{
    int warp = blockIdx.x * (blockDim.x >> 5) + (threadIdx.x >> 5);
    int lane = threadIdx.x & 31;
    if (warp >= R_ALL) return;
    const __half* x = X + (size_t)warp * HID;
    float s = 0.0f;
    #pragma unroll
    for (int k = lane; k < HID; k += 32)
        s = fmaf(__half2float(x[k]), Wv[k], s);
    #pragma unroll
    for (int o = 16; o > 0; o >>= 1) s += __shfl_down_sync(0xFFFFFFFFu, s, o);
    if (lane == 0) v[warp] = s + bv[0];
}

__global__ void score_kernel(const float* __restrict__ v,
                             const float* __restrict__ Ws,
                             const float* __restrict__ bs,
                             float* __restrict__ out)
{
    __shared__ float red[256];
    int b = blockIdx.x;
    int m = threadIdx.x;
    const float* vb = v + ((size_t)b * MROWS + m) * NSEQ;
    float s = 0.0f;
    #pragma unroll
    for (int n = 0; n < NSEQ; n++) s = fmaf(vb[n], Ws[n], s);
    red[m] = s;
    __syncthreads();
    for (int st = 128; st > 0; st >>= 1) {
        if (m < st) red[m] += red[m + st];
        __syncthreads();
    }
    if (m == 0) out[b] = bs[0] + red[0] * (1.0f / (float)MROWS);
}

// ---------------------------------------------------------------------------
// Host orchestration
// ---------------------------------------------------------------------------
template<typename T>
static T* sym_addr(const void* symbol)
{
    void* p = nullptr;
    cudaGetSymbolAddress(&p, symbol);
    return (T*)p;
}

extern "C" void kernel_launch(void* const* d_in, const int* in_sizes, int n_in,
                              void* d_out, int out_size)
{
    const float* swin = (const float*)d_in[0];
    const float* conv = (const float*)d_in[1];
    const float* Wc   = (const float*)d_in[2];
    const float* bc   = (const float*)d_in[3];
    const float* Win  = (const float*)d_in[4];
    const float* b_in = (const float*)d_in[5];
    const float* Wih  = (const float*)d_in[6];
    const float* Whh  = (const float*)d_in[7];
    const float* bih  = (const float*)d_in[8];
    const float* bhh  = (const float*)d_in[9];
    const float* Wv   = (const float*)d_in[10];
    const float* bv   = (const float*)d_in[11];
    const float* Ws   = (const float*)d_in[12];
    const float* bs   = (const float*)d_in[13];
    float* out = (float*)d_out;

    float*  big  = sym_addr<float>(g_big);
    float*  cbuf = sym_addr<float>(g_c);
    float*  vbuf = sym_addr<float>(g_v);
    float*  bsum = sym_addr<float>(g_bsum);
    __half* whi  = sym_addr<__half>(g_whi);
    __half* wlo  = sym_addr<__half>(g_wlo);
    __half* ach  = sym_addr<__half>(g_ach);
    __half* bigh = sym_addr<__half>(g_bigh);
    __half* xh   = sym_addr<__half>(g_xh);

    cudaFuncSetAttribute(fgemm<1,1>, cudaFuncAttributeMaxDynamicSharedMemorySize, SMEM_DYN);
    cudaFuncSetAttribute(fgemm<0,1>, cudaFuncAttributeMaxDynamicSharedMemorySize, SMEM_DYN);
    cudaFuncSetAttribute(fgemm<0,0>, cudaFuncAttributeMaxDynamicSharedMemorySize, SMEM_DYN);
    cudaFuncSetAttribute(fgemm<4,0>, cudaFuncAttributeMaxDynamicSharedMemorySize, SMEM_DYN);

    const dim3 blk(256);

    // ---- prep ----
    convert_act<<<(R_ALL * EMBED / 4 + 255) / 256, blk>>>(conv, ach, R_ALL * EMBED / 4);
    convert_w<<<(1048576 / 4 + 255) / 256, blk>>>(Wc,  whi + WC_OFF,  wlo + WC_OFF,  1024, 1024, 0);
    convert_w<<<(262144  / 4 + 255) / 256, blk>>>(Win, whi + WIN_OFF, wlo + WIN_OFF, 256, 1024, 0);
    for (int l = 0; l < LAYERS; ++l) {
        convert_w<<<(262144 / 4 + 255) / 256, blk>>>(
            Wih + (size_t)l * G4 * INDIM,
            whi + WIH_OFF + (size_t)l * G4 * INDIM,
            wlo + WIH_OFF + (size_t)l * G4 * INDIM, G4, INDIM, 1);
        convert_w<<<(262144 / 4 + 255) / 256, blk>>>(
            Whh + (size_t)l * G4 * HID,
            whi + WHH_OFF + (size_t)l * G4 * HID,
            wlo + WHH_OFF + (size_t)l * G4 * HID, G4, HID, 1);
    }
    bias_perm<<<(LAYERS * G4 + 255) / 256, blk>>>(bih, bhh, bsum);

    // Stage 1: bigh = fp16(swin + gelu(conv @ Wc^T + bc))   K=1024
    {
        dim3 grid(EMBED / TILE_N, R_ALL / TILE_M);
        fgemm<1,1><<<grid, blk, SMEM_DYN>>>(ach, EMBED,
                                            whi + WC_OFF, wlo + WC_OFF, EMBED, EMBED,
                                            nullptr, bigh, EMBED,
                                            bc, swin, EMBED,
                                            nullptr, nullptr, 0);
    }
    // Stage 2: xh = fp16(big @ Win^T + b_in)                K=1024
    {
        dim3 grid(INDIM / TILE_N, R_ALL / TILE_M);
        fgemm<0,1><<<grid, blk, SMEM_DYN>>>(bigh, EMBED,
                                            whi + WIN_OFF, wlo + WIN_OFF, EMBED, EMBED,
                                            nullptr, xh, INDIM,
                                            b_in, nullptr, 0,
                                            nullptr, nullptr, 0);
    }

    for (int l = 0; l < LAYERS; ++l) {
        const __half* Wih_h = whi + WIH_OFF + (size_t)l * G4 * INDIM;
        const __half* Wih_l = wlo + WIH_OFF + (size_t)l * G4 * INDIM;
        const __half* Whh_h = whi + WHH_OFF + (size_t)l * G4 * HID;
        const __half* Whh_l = wlo + WHH_OFF + (size_t)l * G4 * HID;

        // Gin = xseq @ Wih^T + (bih+bhh)  (interleaved cols)  K=256
        {
            dim3 grid(G4 / TILE_N, R_ALL / TILE_M);
            fgemm<0,0><<<grid, blk, SMEM_DYN>>>(xh, INDIM,
                                                Wih_h, Wih_l, INDIM, INDIM,
                                                big, nullptr, G4,
                                                bsum + l * G4, nullptr, 0,
                                                nullptr, nullptr, 0);
        }

        // t = 0: h0 = c0 = 0 -> cell directly on Gin
        lstm_t0<<<(BMR * HID + 255) / 256, blk>>>(big, NSEQ * G4, cbuf, xh);

        // t >= 1: fused recurrent GEMM + cell; A = xseq slot t-1
        for (int t = 1; t < NSEQ; ++t) {
            dim3 grid(G4 / TILE_N, BMR / TILE_M);
            fgemm<4,0><<<grid, blk, SMEM_DYN>>>(xh + (size_t)(t - 1) * HID, NSEQ * HID,
                                                Whh_h, Whh_l, HID, HID,
                                                nullptr, nullptr, 0,
                                                nullptr,
                                                big + (size_t)t * G4, NSEQ * G4,
                                                cbuf, xh, t);
        }
    }

    viewport_kernel<<<R_ALL / 8, blk>>>(xh, Wv, bv, vbuf);
    score_kernel<<<BATCH, blk>>>(vbuf, Ws, bs, out);
    (void)in_sizes; (void)n_in; (void)out_size;
}